// round 1
// baseline (speedup 1.0000x reference)
#include <cuda_runtime.h>
#include <cstdint>

#define Bdim 32
#define Kdim 17
#define Hdim 160
#define Wdim 160
#define HW   (Hdim*Wdim)
#define Pn   30
#define Sn   10
#define Ln   19
#define CAP  6656
#define T1   256
#define T2   512

__constant__ int c_skel_a[Ln] = {15,13,16,14,11, 5, 6, 5, 5, 6, 7, 8, 1, 0, 0, 1, 2, 3, 4};
__constant__ int c_skel_b[Ln] = {13,11,14,12,12,11,12, 6, 7, 8, 9,10, 2, 1, 2, 3, 4, 5, 6};

// ---------------------------------------------------------------------------
// Stage 1: per-(b,k) channel — 3x3 NMS peak detect + top-30 + subpixel refine
// dynamic smem: heat tile (HW floats) + candidate keys (CAP u64)
// ---------------------------------------------------------------------------
__global__ void stage1_kernel(const float* __restrict__ heat, float* __restrict__ out_peaks)
{
    extern __shared__ char s_raw[];
    float* hs = (float*)s_raw;                                        // HW floats
    unsigned long long* cand = (unsigned long long*)(s_raw + HW * 4); // CAP keys

    __shared__ int cnt;
    __shared__ unsigned long long wk[T1 / 32];
    __shared__ int wp[T1 / 32];

    const int bk = blockIdx.x;                 // b*K + k
    const float* hp = heat + (size_t)bk * HW;

    // coalesced load of the whole channel into smem
    for (int i = threadIdx.x; i < HW / 4; i += T1)
        ((float4*)hs)[i] = ((const float4*)hp)[i];
    if (threadIdx.x == 0) cnt = 0;
    __syncthreads();

    // peak detection: h strictly > 0.1 and h >= all in-bounds 8-neighbors
    for (int i = threadIdx.x; i < HW; i += T1) {
        float h = hs[i];
        if (h > 0.1f) {
            int y = i / Wdim;
            int x = i - y * Wdim;
            bool pk = true;
            bool xl = (x > 0), xr = (x < Wdim - 1);
            if (xl && hs[i - 1] > h) pk = false;
            if (pk && xr && hs[i + 1] > h) pk = false;
            if (pk && y > 0) {
                int j = i - Wdim;
                if (hs[j] > h) pk = false;
                if (pk && xl && hs[j - 1] > h) pk = false;
                if (pk && xr && hs[j + 1] > h) pk = false;
            }
            if (pk && y < Hdim - 1) {
                int j = i + Wdim;
                if (hs[j] > h) pk = false;
                if (pk && xl && hs[j - 1] > h) pk = false;
                if (pk && xr && hs[j + 1] > h) pk = false;
            }
            if (pk) {
                int p = atomicAdd(&cnt, 1);
                if (p < CAP) {
                    unsigned long long key =
                        ((unsigned long long)__float_as_uint(h) << 32) |
                        (unsigned long long)(0xFFFFFFFFu - (unsigned)i);
                    cand[p] = key;
                }
            }
        }
    }
    __syncthreads();

    int n = cnt < CAP ? cnt : CAP;

    // 30 rounds of block-wide argmax over the candidate keys
    for (int p = 0; p < Pn; ++p) {
        unsigned long long best = 0ull;
        int bpos = -1;
        for (int i = threadIdx.x; i < n; i += T1) {
            unsigned long long c = cand[i];
            if (c > best) { best = c; bpos = i; }
        }
        // warp reduce (key, pos)
        #pragma unroll
        for (int off = 16; off > 0; off >>= 1) {
            unsigned long long ob = __shfl_down_sync(0xffffffffu, best, off);
            int op = __shfl_down_sync(0xffffffffu, bpos, off);
            if (ob > best) { best = ob; bpos = op; }
        }
        if ((threadIdx.x & 31) == 0) {
            wk[threadIdx.x >> 5] = best;
            wp[threadIdx.x >> 5] = bpos;
        }
        __syncthreads();
        if (threadIdx.x == 0) {
            for (int w = 1; w < T1 / 32; ++w)
                if (wk[w] > best) { best = wk[w]; bpos = wp[w]; }

            float px = 0.f, py = 0.f, sc = 0.f;
            if (best != 0ull) {
                cand[bpos] = 0ull;  // remove winner
                unsigned idx = 0xFFFFFFFFu - (unsigned)(best & 0xFFFFFFFFu);
                float h = __uint_as_float((unsigned)(best >> 32));
                int y = idx / Wdim;
                int x = idx - y * Wdim;
                float dx = 0.f, dy = 0.f;
                if (y > 0 && y < Hdim - 1 && x > 0 && x < Wdim - 1) {
                    float r = hs[idx + 1], l = hs[idx - 1];
                    float d = hs[idx + Wdim], u = hs[idx - Wdim];
                    float dxr = 0.5f * (r - l);
                    float dxx = (r + l) - 2.0f * h;
                    dx = (fabsf(dxx) > 1e-6f) ? (dxr / (-dxx)) : dxr;
                    float dyr = 0.5f * (d - u);
                    float dyy = (d + u) - 2.0f * h;
                    dy = (fabsf(dyy) > 1e-6f) ? (dyr / (-dyy)) : dyr;
                }
                px = (float)x + dx;
                py = (float)y + dy;
                sc = h;
            }
            float* o = out_peaks + ((size_t)bk * Pn + p) * 3;
            o[0] = px; o[1] = py; o[2] = sc;
        }
        __syncthreads();
    }
}

// ---------------------------------------------------------------------------
// Stage 2: per-(b,l) limb — PAF line-integral scoring over 30x30 peak pairs
// dynamic smem: pafx (HW) + pafy (HW) floats
// ---------------------------------------------------------------------------
__global__ void stage2_kernel(const float* __restrict__ paf,
                              const float* __restrict__ peaks,
                              float* __restrict__ conn)
{
    extern __shared__ float s2[];
    float* pafx = s2;
    float* pafy = s2 + HW;

    __shared__ float sax[Pn], say[Pn], sas[Pn];
    __shared__ float sbx[Pn], sby[Pn], sbs[Pn];

    const int bl = blockIdx.x;      // b*Ln + l
    const int b = bl / Ln;
    const int l = bl - b * Ln;

    const float* gx = paf + ((size_t)b * 38 + 2 * l) * HW;
    const float* gy = paf + ((size_t)b * 38 + 2 * l + 1) * HW;
    for (int i = threadIdx.x; i < HW / 4; i += T2) {
        ((float4*)pafx)[i] = ((const float4*)gx)[i];
        ((float4*)pafy)[i] = ((const float4*)gy)[i];
    }

    const int ja = c_skel_a[l];
    const int jb = c_skel_b[l];
    if (threadIdx.x < Pn) {
        const float* pa = peaks + ((size_t)(b * Kdim + ja) * Pn + threadIdx.x) * 3;
        sax[threadIdx.x] = pa[0];
        say[threadIdx.x] = pa[1];
        sas[threadIdx.x] = pa[2];
    } else if (threadIdx.x >= 32 && threadIdx.x < 32 + Pn) {
        int j = threadIdx.x - 32;
        const float* pb = peaks + ((size_t)(b * Kdim + jb) * Pn + j) * 3;
        sbx[j] = pb[0];
        sby[j] = pb[1];
        sbs[j] = pb[2];
    }
    __syncthreads();

    float* co = conn + (size_t)bl * Pn * Pn;
    const float step = 1.0f / 9.0f;

    for (int pr = threadIdx.x; pr < Pn * Pn; pr += T2) {
        const int i = pr / Pn;
        const int j = pr - i * Pn;
        float ax = sax[i], ay = say[i], sa = sas[i];
        float bx = sbx[j], by = sby[j], sb = sbs[j];
        float outv = 0.0f;
        if (sa > 0.1f && sb > 0.1f) {
            float dxl = bx - ax;
            float dyl = by - ay;
            float norm = sqrtf(__fadd_rn(__fmul_rn(dxl, dxl), __fmul_rn(dyl, dyl))) + 1e-8f;
            float vx = dxl / norm;
            float vy = dyl / norm;
            float sum = 0.0f;
            int c = 0;
            #pragma unroll
            for (int s = 0; s < Sn; ++s) {
                float t = (float)s * step;
                // keep mul+add separate (no fma) to match XLA elementwise ops,
                // since a ulp flip at a .5 boundary changes the gathered cell
                float xs = __fadd_rn(ax, __fmul_rn(t, dxl));
                float ys = __fadd_rn(ay, __fmul_rn(t, dyl));
                float fx = fminf(fmaxf(rintf(xs), 0.0f), (float)(Wdim - 1));
                float fy = fminf(fmaxf(rintf(ys), 0.0f), (float)(Hdim - 1));
                int lin = (int)fy * Wdim + (int)fx;
                float v = __fadd_rn(__fmul_rn(pafx[lin], vx), __fmul_rn(pafy[lin], vy));
                sum = __fadd_rn(sum, v);
                c += (v > 0.05f) ? 1 : 0;
            }
            float mean = sum / 10.0f;
            float ratio = (float)c / 10.0f;
            if (mean > 0.0f && ratio > 0.8f)
                outv = mean + 0.5f * (sa + sb);
        }
        co[pr] = outv;
    }
}

// ---------------------------------------------------------------------------
extern "C" void kernel_launch(void* const* d_in, const int* in_sizes, int n_in,
                              void* d_out, int out_size)
{
    const float* heat = (const float*)d_in[0];
    const float* paf  = (const float*)d_in[1];
    float* out   = (float*)d_out;
    float* peaks = out;                                  // B*K*P*3 = 48960
    float* conn  = out + (size_t)Bdim * Kdim * Pn * 3;   // B*L*P*P = 547200

    const int smem1 = HW * 4 + CAP * 8;   // 155648
    const int smem2 = 2 * HW * 4;         // 204800
    cudaFuncSetAttribute(stage1_kernel, cudaFuncAttributeMaxDynamicSharedMemorySize, smem1);
    cudaFuncSetAttribute(stage2_kernel, cudaFuncAttributeMaxDynamicSharedMemorySize, smem2);

    stage1_kernel<<<Bdim * Kdim, T1, smem1>>>(heat, peaks);
    stage2_kernel<<<Bdim * Ln, T2, smem2>>>(paf, peaks, conn);
}

// round 2
// speedup vs baseline: 1.4037x; 1.4037x over previous
#include <cuda_runtime.h>
#include <cstdint>

#define Bdim 32
#define Kdim 17
#define Hdim 160
#define Wdim 160
#define HW   (Hdim*Wdim)
#define Pn   30
#define Sn   10
#define Ln   19
#define T1   256
#define T2   512
#define NBINS 2048
#define CCAP  512

__constant__ int c_skel_a[Ln] = {15,13,16,14,11, 5, 6, 5, 5, 6, 7, 8, 1, 0, 0, 1, 2, 3, 4};
__constant__ int c_skel_b[Ln] = {13,11,14,12,12,11,12, 6, 7, 8, 9,10, 2, 1, 2, 3, 4, 5, 6};

// ---------------- cp.async helpers ----------------
__device__ __forceinline__ void cp16(void* s, const void* g) {
    unsigned sa = (unsigned)__cvta_generic_to_shared(s);
    asm volatile("cp.async.cg.shared.global [%0], [%1], 16;\n" :: "r"(sa), "l"(g));
}
__device__ __forceinline__ void cp_commit() {
    asm volatile("cp.async.commit_group;\n");
}
template <int N>
__device__ __forceinline__ void cp_wait() {
    asm volatile("cp.async.wait_group %0;\n" :: "n"(N));
}

// ---------------- stage 1 helpers ----------------
// matches lax.reduce_window(max, 3x3, SAME): h is a peak iff no in-bounds
// neighbor is strictly greater.  Clamp-to-center trick: OOB neighbor index
// replaced by i itself (value h, and h > h is false).
__device__ __forceinline__ bool is_peak(const float* __restrict__ hs, int i, int x, int y, float h) {
    int xl = (x > 0) ? 1 : 0;
    int xr = (x < Wdim - 1) ? 1 : 0;
    int yu = (y > 0) ? Wdim : 0;
    int yd = (y < Hdim - 1) ? Wdim : 0;
    float m0 = fmaxf(hs[i - xl],       hs[i + xr]);
    float m1 = fmaxf(hs[i - yu],       hs[i + yd]);
    float m2 = fmaxf(hs[i - yu - xl],  hs[i - yu + xr]);
    float m3 = fmaxf(hs[i + yd - xl],  hs[i + yd + xr]);
    float mm = fmaxf(fmaxf(m0, m1), fmaxf(m2, m3));
    return mm <= h;
}

// monotone bin: v = h^9 (uniform-izes max-of-9-like peak-score distribution)
__device__ __forceinline__ int bin_of(float h) {
    float h2 = h * h;
    float h4 = h2 * h2;
    float h8 = h4 * h4;
    float v  = h8 * h;
    int b = (int)(v * (float)NBINS);
    return b < 0 ? 0 : (b > NBINS - 1 ? NBINS - 1 : b);
}

// ---------------------------------------------------------------------------
// Stage 1: per-(b,k) channel — NMS peaks + histogram radix-select top-30
// dynamic smem: heat tile (HW f32) + hist (NBINS u32) + collect list (CCAP u64)
// ---------------------------------------------------------------------------
__global__ void stage1_kernel(const float* __restrict__ heat, float* __restrict__ out_peaks)
{
    extern __shared__ char s_raw[];
    float* hs = (float*)s_raw;                                         // HW
    unsigned* hist = (unsigned*)(s_raw + HW * 4);                      // NBINS
    unsigned long long* list = (unsigned long long*)(s_raw + HW * 4 + NBINS * 4); // CCAP

    __shared__ int s_cut;
    __shared__ int s_m;
    __shared__ unsigned long long s_top[Pn];

    const int bk = blockIdx.x;
    const float* hp = heat + (size_t)bk * HW;

    // async tile load; zero histogram meanwhile
    for (int i = threadIdx.x; i < HW / 4; i += T1)
        cp16(&((float4*)hs)[i], &((const float4*)hp)[i]);
    cp_commit();
    for (int i = threadIdx.x; i < NBINS; i += T1) hist[i] = 0;
    if (threadIdx.x == 0) { s_m = 0; s_cut = 0; }
    cp_wait<0>();
    __syncthreads();

    // pass 1: detect + histogram (sparse atomics, branch only on ~10% miss)
    for (int i = threadIdx.x; i < HW; i += T1) {
        float h = hs[i];
        if (h > 0.1f) {
            int y = i / Wdim;
            int x = i - y * Wdim;
            if (is_peak(hs, i, x, y, h))
                atomicAdd(&hist[bin_of(h)], 1u);
        }
    }
    __syncthreads();

    // warp 0: find cutoff bin (suffix-count from top until >= Pn)
    if (threadIdx.x < 32) {
        int lane = threadIdx.x;
        int acc = 0;
        int cut = 0;
        for (int base = NBINS - 32; base >= 0; base -= 32) {
            int s = (int)hist[base + lane];
            #pragma unroll
            for (int off = 1; off < 32; off <<= 1) {
                int t = __shfl_down_sync(0xffffffffu, s, off);
                if (lane + off < 32) s += t;
            }
            int chunk_total = __shfl_sync(0xffffffffu, s, 0);
            if (acc + chunk_total >= Pn) {
                unsigned mask = __ballot_sync(0xffffffffu, acc + s >= Pn);
                cut = base + (31 - __clz(mask));
                break;
            }
            acc += chunk_total;
        }
        if (lane == 0) s_cut = cut;
    }
    __syncthreads();

    // pass 2: collect candidates with bin >= cutoff (expected ~Pn + few)
    const int cut = s_cut;
    for (int i = threadIdx.x; i < HW; i += T1) {
        float h = hs[i];
        if (h > 0.1f) {
            int y = i / Wdim;
            int x = i - y * Wdim;
            if (is_peak(hs, i, x, y, h) && bin_of(h) >= cut) {
                int p = atomicAdd(&s_m, 1);
                if (p < CCAP) {
                    list[p] = ((unsigned long long)__float_as_uint(h) << 32) |
                              (unsigned long long)(0xFFFFFFFFu - (unsigned)i);
                }
            }
        }
    }
    __syncthreads();

    // warp 0: 30 argmax rounds over tiny list (no block barriers)
    if (threadIdx.x < 32) {
        const int lane = threadIdx.x;
        const int m = (s_m < CCAP) ? s_m : CCAP;
        for (int p = 0; p < Pn; ++p) {
            unsigned long long best = 0ull;
            int bpos = -1;
            for (int i = lane; i < m; i += 32) {
                unsigned long long c = list[i];
                if (c > best) { best = c; bpos = i; }
            }
            #pragma unroll
            for (int off = 16; off > 0; off >>= 1) {
                unsigned long long ob = __shfl_down_sync(0xffffffffu, best, off);
                int op = __shfl_down_sync(0xffffffffu, bpos, off);
                if (ob > best) { best = ob; bpos = op; }
            }
            best = __shfl_sync(0xffffffffu, best, 0);
            bpos = __shfl_sync(0xffffffffu, bpos, 0);
            if (lane == 0) {
                s_top[p] = best;
                if (bpos >= 0) list[bpos] = 0ull;
            }
            __syncwarp();
        }

        // subpixel refine + emit (lanes 0..29), still warp 0 so syncwarp is enough
        if (lane < Pn) {
            unsigned long long key = s_top[lane];
            float px = 0.f, py = 0.f, sc = 0.f;
            if (key != 0ull) {
                unsigned idx = 0xFFFFFFFFu - (unsigned)(key & 0xFFFFFFFFu);
                float h = __uint_as_float((unsigned)(key >> 32));
                int y = idx / Wdim;
                int x = idx - y * Wdim;
                float dx = 0.f, dy = 0.f;
                if (y > 0 && y < Hdim - 1 && x > 0 && x < Wdim - 1) {
                    float r = hs[idx + 1],    l = hs[idx - 1];
                    float d = hs[idx + Wdim], u = hs[idx - Wdim];
                    float dxr = 0.5f * (r - l);
                    float dxx = (r + l) - 2.0f * h;
                    dx = (fabsf(dxx) > 1e-6f) ? (dxr / (-dxx)) : dxr;
                    float dyr = 0.5f * (d - u);
                    float dyy = (d + u) - 2.0f * h;
                    dy = (fabsf(dyy) > 1e-6f) ? (dyr / (-dyy)) : dyr;
                }
                px = (float)x + dx;
                py = (float)y + dy;
                sc = h;
            }
            float* o = out_peaks + ((size_t)bk * Pn + lane) * 3;
            o[0] = px; o[1] = py; o[2] = sc;
        }
    }
}

// ---------------------------------------------------------------------------
// Stage 2: per-(b,l) limb — PAF line scoring, cp.async double-group pipeline
// dynamic smem: pafx (HW) + pafy (HW) floats
// ---------------------------------------------------------------------------
__global__ void __launch_bounds__(T2) stage2_kernel(const float* __restrict__ paf,
                                                    const float* __restrict__ peaks,
                                                    float* __restrict__ conn)
{
    extern __shared__ float s2[];
    float* pafx = s2;
    float* pafy = s2 + HW;

    __shared__ float sax[Pn], say[Pn], sas[Pn];
    __shared__ float sbx[Pn], sby[Pn], sbs[Pn];

    const int bl = blockIdx.x;      // b*Ln + l
    const int b = bl / Ln;
    const int l = bl - b * Ln;

    const float4* gx = (const float4*)(paf + ((size_t)b * 38 + 2 * l) * HW);
    const float4* gy = (const float4*)(paf + ((size_t)b * 38 + 2 * l + 1) * HW);

    // group A: pafx ; group B: pafy
    for (int i = threadIdx.x; i < HW / 4; i += T2)
        cp16(&((float4*)pafx)[i], &gx[i]);
    cp_commit();
    for (int i = threadIdx.x; i < HW / 4; i += T2)
        cp16(&((float4*)pafy)[i], &gy[i]);
    cp_commit();

    // stage the two peak sets while loads fly
    const int ja = c_skel_a[l];
    const int jb = c_skel_b[l];
    if (threadIdx.x < Pn) {
        const float* pa = peaks + ((size_t)(b * Kdim + ja) * Pn + threadIdx.x) * 3;
        sax[threadIdx.x] = pa[0]; say[threadIdx.x] = pa[1]; sas[threadIdx.x] = pa[2];
    } else if (threadIdx.x >= 32 && threadIdx.x < 32 + Pn) {
        int j = threadIdx.x - 32;
        const float* pb = peaks + ((size_t)(b * Kdim + jb) * Pn + j) * 3;
        sbx[j] = pb[0]; sby[j] = pb[1]; sbs[j] = pb[2];
    }

    cp_wait<1>();          // pafx resident
    __syncthreads();

    // per-thread state for up to 2 pairs (kept fully unrolled -> registers)
    int   lin[2][Sn];
    float xp [2][Sn];
    float vyv[2];
    float halfs[2];
    bool  pv[2];
    const float step = 1.0f / 9.0f;

    #pragma unroll
    for (int q = 0; q < 2; ++q) {
        int pr = threadIdx.x + q * T2;
        bool act = (pr < Pn * Pn);
        int i = act ? (pr / Pn) : 0;
        int j = act ? (pr - i * Pn) : 0;
        float ax = sax[i], ay = say[i], sa = sas[i];
        float bx = sbx[j], by = sby[j], sb = sbs[j];
        bool valid = act && (sa > 0.1f) && (sb > 0.1f);
        pv[q] = valid;
        halfs[q] = 0.5f * (sa + sb);
        float dxl = bx - ax;
        float dyl = by - ay;
        float norm = sqrtf(__fadd_rn(__fmul_rn(dxl, dxl), __fmul_rn(dyl, dyl))) + 1e-8f;
        float vx = dxl / norm;
        float vy = dyl / norm;
        vyv[q] = vy;
        #pragma unroll
        for (int s = 0; s < Sn; ++s) {
            float t = (float)s * step;
            // no-FMA: a ulp flip at a .5 boundary changes the gathered cell
            float xs = __fadd_rn(ax, __fmul_rn(t, dxl));
            float ys = __fadd_rn(ay, __fmul_rn(t, dyl));
            float fx = fminf(fmaxf(rintf(xs), 0.0f), (float)(Wdim - 1));
            float fy = fminf(fmaxf(rintf(ys), 0.0f), (float)(Hdim - 1));
            int li = valid ? ((int)fy * Wdim + (int)fx) : 0;
            lin[q][s] = li;
            xp[q][s] = __fmul_rn(pafx[li], vx);
        }
    }

    cp_wait<0>();          // pafy resident
    __syncthreads();

    float* co = conn + (size_t)bl * Pn * Pn;
    #pragma unroll
    for (int q = 0; q < 2; ++q) {
        int pr = threadIdx.x + q * T2;
        bool act = (pr < Pn * Pn);
        float sum = 0.0f;
        int c = 0;
        #pragma unroll
        for (int s = 0; s < Sn; ++s) {
            float v = __fadd_rn(xp[q][s], __fmul_rn(pafy[lin[q][s]], vyv[q]));
            sum = __fadd_rn(sum, v);
            c += (v > 0.05f) ? 1 : 0;
        }
        float outv = 0.0f;
        if (pv[q]) {
            float mean = sum / 10.0f;
            float ratio = (float)c / 10.0f;
            if (mean > 0.0f && ratio > 0.8f)
                outv = mean + halfs[q];
        }
        if (act) co[pr] = outv;
    }
}

// ---------------------------------------------------------------------------
extern "C" void kernel_launch(void* const* d_in, const int* in_sizes, int n_in,
                              void* d_out, int out_size)
{
    const float* heat = (const float*)d_in[0];
    const float* paf  = (const float*)d_in[1];
    float* out   = (float*)d_out;
    float* peaks = out;                                  // B*K*P*3 = 48960
    float* conn  = out + (size_t)Bdim * Kdim * Pn * 3;   // B*L*P*P = 547200

    const int smem1 = HW * 4 + NBINS * 4 + CCAP * 8;     // 114688 -> 2 blocks/SM
    const int smem2 = 2 * HW * 4;                        // 204800
    cudaFuncSetAttribute(stage1_kernel, cudaFuncAttributeMaxDynamicSharedMemorySize, smem1);
    cudaFuncSetAttribute(stage2_kernel, cudaFuncAttributeMaxDynamicSharedMemorySize, smem2);

    stage1_kernel<<<Bdim * Kdim, T1, smem1>>>(heat, peaks);
    stage2_kernel<<<Bdim * Ln, T2, smem2>>>(paf, peaks, conn);
}

// round 3
// speedup vs baseline: 3.7788x; 2.6920x over previous
#include <cuda_runtime.h>
#include <cstdint>

#define Bdim 32
#define Kdim 17
#define Hdim 160
#define Wdim 160
#define HW   (Hdim*Wdim)
#define W4   (Wdim/4)
#define NG   (HW/4)
#define Pn   30
#define Sn   10
#define Ln   19
#define T1   256
#define T2   512
#define NBINS 1024
#define CAP   6144
#define SCAP  128
#define NEGF  (-1.0e30f)

__constant__ int c_skel_a[Ln] = {15,13,16,14,11, 5, 6, 5, 5, 6, 7, 8, 1, 0, 0, 1, 2, 3, 4};
__constant__ int c_skel_b[Ln] = {13,11,14,12,12,11,12, 6, 7, 8, 9,10, 2, 1, 2, 3, 4, 5, 6};

// ---------------- cp.async helpers ----------------
__device__ __forceinline__ void cp16(void* s, const void* g) {
    unsigned sa = (unsigned)__cvta_generic_to_shared(s);
    asm volatile("cp.async.cg.shared.global [%0], [%1], 16;\n" :: "r"(sa), "l"(g));
}
__device__ __forceinline__ void cp_commit() { asm volatile("cp.async.commit_group;\n"); }
template <int N>
__device__ __forceinline__ void cp_wait() { asm volatile("cp.async.wait_group %0;\n" :: "n"(N)); }

// monotone bin: v = h^9 (uniform-izes max-of-9 peak-score distribution)
__device__ __forceinline__ int bin_of(float h) {
    float h2 = h * h;
    float h4 = h2 * h2;
    float v  = h4 * h4 * h;
    int b = (int)(v * (float)NBINS);
    return b < 0 ? 0 : (b > NBINS - 1 ? NBINS - 1 : b);
}

__device__ __forceinline__ float max3(float a, float b, float c) {
    return fmaxf(fmaxf(a, b), c);
}

// ---------------------------------------------------------------------------
// Stage 1: per-(b,k) channel.  Global-memory vectorized NMS -> candidate list
// (warp-aggregated) -> histogram radix-select over the LIST -> warp argmax.
// dynamic smem: list (CAP u64) + hist (NBINS u32)
// ---------------------------------------------------------------------------
__global__ void __launch_bounds__(T1) stage1_kernel(const float* __restrict__ heat,
                                                    float* __restrict__ out_peaks)
{
    extern __shared__ char s_raw[];
    unsigned long long* list = (unsigned long long*)s_raw;            // CAP
    unsigned* hist = (unsigned*)(s_raw + CAP * 8);                    // NBINS

    __shared__ unsigned long long surv[SCAP];
    __shared__ int s_m, s_sc, s_cut;

    const int bk = blockIdx.x;
    const float* hp = heat + (size_t)bk * HW;
    const float4* hp4 = (const float4*)hp;
    const int lane = threadIdx.x & 31;

    for (int i = threadIdx.x; i < NBINS; i += T1) hist[i] = 0;
    if (threadIdx.x == 0) { s_m = 0; s_sc = 0; s_cut = 0; }
    __syncthreads();

    // ---- detection pass: 4 pixels/thread-iter, branchless edge handling ----
    for (int g = threadIdx.x; g < NG; g += T1) {
        int y  = g / W4;
        int xq = g - y * W4;
        int i  = g * 4;                       // linear index of first pixel
        bool up = (y > 0), dn = (y < Hdim - 1);
        bool lf = (xq > 0), rt = (xq < W4 - 1);

        float4 C = hp4[g];
        float4 U = up ? hp4[g - W4] : make_float4(NEGF, NEGF, NEGF, NEGF);
        float4 D = dn ? hp4[g + W4] : make_float4(NEGF, NEGF, NEGF, NEGF);
        float lC =  lf        ? __ldg(hp + i - 1)        : NEGF;
        float rC =  rt        ? __ldg(hp + i + 4)        : NEGF;
        float lU = (lf && up) ? __ldg(hp + i - Wdim - 1) : NEGF;
        float rU = (rt && up) ? __ldg(hp + i - Wdim + 4) : NEGF;
        float lD = (lf && dn) ? __ldg(hp + i + Wdim - 1) : NEGF;
        float rD = (rt && dn) ? __ldg(hp + i + Wdim + 4) : NEGF;

        float wU[6] = {lU, U.x, U.y, U.z, U.w, rU};
        float wC[6] = {lC, C.x, C.y, C.z, C.w, rC};
        float wD[6] = {lD, D.x, D.y, D.z, D.w, rD};

        #pragma unroll
        for (int j = 0; j < 4; ++j) {
            float h  = wC[j + 1];
            float nm = fmaxf(max3(wU[j], wU[j + 1], wU[j + 2]),
                             fmaxf(max3(wD[j], wD[j + 1], wD[j + 2]),
                                   fmaxf(wC[j], wC[j + 2])));
            bool pk = (h > 0.1f) && (nm <= h);
            unsigned mask = __ballot_sync(0xffffffffu, pk);
            if (pk) {
                int leader = __ffs(mask) - 1;
                int base;
                if (lane == leader) base = atomicAdd(&s_m, __popc(mask));
                base = __shfl_sync(mask, base, leader);
                int pos = base + __popc(mask & ((1u << lane) - 1u));
                if (pos < CAP) {
                    list[pos] = ((unsigned long long)__float_as_uint(h) << 32) |
                                (unsigned long long)(0xFFFFFFFFu - (unsigned)(i + j));
                }
            }
        }
    }
    __syncthreads();

    const int m = (s_m < CAP) ? s_m : CAP;

    // ---- histogram over the candidate list ----
    for (int i = threadIdx.x; i < m; i += T1) {
        float h = __uint_as_float((unsigned)(list[i] >> 32));
        atomicAdd(&hist[bin_of(h)], 1u);
    }
    __syncthreads();

    // ---- warp 0: cutoff bin = highest bin whose suffix count >= Pn ----
    if (threadIdx.x < 32) {
        int acc = 0, cut = 0;
        for (int base = NBINS - 32; base >= 0; base -= 32) {
            int s = (int)hist[base + lane];
            #pragma unroll
            for (int off = 1; off < 32; off <<= 1) {
                int t = __shfl_down_sync(0xffffffffu, s, off);
                if (lane + off < 32) s += t;
            }
            int chunk_total = __shfl_sync(0xffffffffu, s, 0);
            if (acc + chunk_total >= Pn) {
                unsigned msk = __ballot_sync(0xffffffffu, acc + s >= Pn);
                cut = base + (31 - __clz(msk));
                break;
            }
            acc += chunk_total;
        }
        if (lane == 0) s_cut = cut;
    }
    __syncthreads();

    // ---- compact survivors (bin >= cut), warp-aggregated ----
    const int cut = s_cut;
    const int m_pad = (m + T1 - 1) / T1 * T1;
    for (int i = threadIdx.x; i < m_pad; i += T1) {
        bool keep = false;
        unsigned long long key = 0ull;
        if (i < m) {
            key = list[i];
            keep = bin_of(__uint_as_float((unsigned)(key >> 32))) >= cut;
        }
        unsigned mask = __ballot_sync(0xffffffffu, keep);
        if (keep) {
            int leader = __ffs(mask) - 1;
            int base;
            if (lane == leader) base = atomicAdd(&s_sc, __popc(mask));
            base = __shfl_sync(mask, base, leader);
            int pos = base + __popc(mask & ((1u << lane) - 1u));
            if (pos < SCAP) surv[pos] = key;
        }
    }
    __syncthreads();

    // ---- warp 0: 30 argmax rounds over tiny survivor set + refine ----
    if (threadIdx.x < 32) {
        const int n = (s_sc < SCAP) ? s_sc : SCAP;
        __shared__ unsigned long long s_top[Pn];
        for (int p = 0; p < Pn; ++p) {
            unsigned long long best = 0ull;
            int bpos = -1;
            for (int i = lane; i < n; i += 32) {
                unsigned long long c = surv[i];
                if (c > best) { best = c; bpos = i; }
            }
            #pragma unroll
            for (int off = 16; off > 0; off >>= 1) {
                unsigned long long ob = __shfl_down_sync(0xffffffffu, best, off);
                int op = __shfl_down_sync(0xffffffffu, bpos, off);
                if (ob > best) { best = ob; bpos = op; }
            }
            best = __shfl_sync(0xffffffffu, best, 0);
            bpos = __shfl_sync(0xffffffffu, bpos, 0);
            if (lane == 0) {
                s_top[p] = best;
                if (bpos >= 0) surv[bpos] = 0ull;
            }
            __syncwarp();
        }

        if (lane < Pn) {
            unsigned long long key = s_top[lane];
            float px = 0.f, py = 0.f, sc = 0.f;
            if (key != 0ull) {
                unsigned idx = 0xFFFFFFFFu - (unsigned)(key & 0xFFFFFFFFu);
                float h = __uint_as_float((unsigned)(key >> 32));
                int y = idx / Wdim;
                int x = idx - y * Wdim;
                float dx = 0.f, dy = 0.f;
                if (y > 0 && y < Hdim - 1 && x > 0 && x < Wdim - 1) {
                    float r = __ldg(hp + idx + 1),    l = __ldg(hp + idx - 1);
                    float d = __ldg(hp + idx + Wdim), u = __ldg(hp + idx - Wdim);
                    float dxr = 0.5f * (r - l);
                    float dxx = (r + l) - 2.0f * h;
                    dx = (fabsf(dxx) > 1e-6f) ? (dxr / (-dxx)) : dxr;
                    float dyr = 0.5f * (d - u);
                    float dyy = (d + u) - 2.0f * h;
                    dy = (fabsf(dyy) > 1e-6f) ? (dyr / (-dyy)) : dyr;
                }
                px = (float)x + dx;
                py = (float)y + dy;
                sc = h;
            }
            float* o = out_peaks + ((size_t)bk * Pn + lane) * 3;
            o[0] = px; o[1] = py; o[2] = sc;
        }
    }
}

// ---------------------------------------------------------------------------
// Stage 2: per-(b,l) limb — one PAF channel in smem at a time (100KB) so two
// blocks co-reside per SM and loads overlap compute across blocks.
// ---------------------------------------------------------------------------
__global__ void __launch_bounds__(T2, 2) stage2_kernel(const float* __restrict__ paf,
                                                       const float* __restrict__ peaks,
                                                       float* __restrict__ conn)
{
    extern __shared__ float s2[];                // HW floats (reused x then y)

    __shared__ float sax[Pn], say[Pn], sas[Pn];
    __shared__ float sbx[Pn], sby[Pn], sbs[Pn];

    const int bl = blockIdx.x;      // b*Ln + l
    const int b = bl / Ln;
    const int l = bl - b * Ln;

    const float4* gx = (const float4*)(paf + ((size_t)b * 38 + 2 * l) * HW);
    const float4* gy = (const float4*)(paf + ((size_t)b * 38 + 2 * l + 1) * HW);

    for (int i = threadIdx.x; i < NG; i += T2)
        cp16(&((float4*)s2)[i], &gx[i]);
    cp_commit();

    const int ja = c_skel_a[l];
    const int jb = c_skel_b[l];
    if (threadIdx.x < Pn) {
        const float* pa = peaks + ((size_t)(b * Kdim + ja) * Pn + threadIdx.x) * 3;
        sax[threadIdx.x] = pa[0]; say[threadIdx.x] = pa[1]; sas[threadIdx.x] = pa[2];
    } else if (threadIdx.x >= 32 && threadIdx.x < 32 + Pn) {
        int j = threadIdx.x - 32;
        const float* pb = peaks + ((size_t)(b * Kdim + jb) * Pn + j) * 3;
        sbx[j] = pb[0]; sby[j] = pb[1]; sbs[j] = pb[2];
    }

    cp_wait<0>();
    __syncthreads();

    int   lin[2][Sn];
    float xp [2][Sn];
    float vyv[2];
    float halfs[2];
    bool  pv[2];
    const float step = 1.0f / 9.0f;

    #pragma unroll
    for (int q = 0; q < 2; ++q) {
        int pr = threadIdx.x + q * T2;
        bool act = (pr < Pn * Pn);
        int i = act ? (pr / Pn) : 0;
        int j = act ? (pr - i * Pn) : 0;
        float ax = sax[i], ay = say[i], sa = sas[i];
        float bx = sbx[j], by = sby[j], sb = sbs[j];
        bool valid = act && (sa > 0.1f) && (sb > 0.1f);
        pv[q] = valid;
        halfs[q] = 0.5f * (sa + sb);
        float dxl = bx - ax;
        float dyl = by - ay;
        float norm = sqrtf(__fadd_rn(__fmul_rn(dxl, dxl), __fmul_rn(dyl, dyl))) + 1e-8f;
        float vx = dxl / norm;
        float vy = dyl / norm;
        vyv[q] = vy;
        #pragma unroll
        for (int s = 0; s < Sn; ++s) {
            float t = (float)s * step;
            // no-FMA: a ulp flip at a .5 boundary changes the gathered cell
            float xs = __fadd_rn(ax, __fmul_rn(t, dxl));
            float ys = __fadd_rn(ay, __fmul_rn(t, dyl));
            float fx = fminf(fmaxf(rintf(xs), 0.0f), (float)(Wdim - 1));
            float fy = fminf(fmaxf(rintf(ys), 0.0f), (float)(Hdim - 1));
            int li = valid ? ((int)fy * Wdim + (int)fx) : 0;
            lin[q][s] = li;
            xp[q][s] = __fmul_rn(s2[li], vx);
        }
    }
    __syncthreads();                 // all pafx reads done; buffer free

    for (int i = threadIdx.x; i < NG; i += T2)
        cp16(&((float4*)s2)[i], &gy[i]);
    cp_commit();
    cp_wait<0>();
    __syncthreads();

    float* co = conn + (size_t)bl * Pn * Pn;
    #pragma unroll
    for (int q = 0; q < 2; ++q) {
        int pr = threadIdx.x + q * T2;
        bool act = (pr < Pn * Pn);
        float sum = 0.0f;
        int c = 0;
        #pragma unroll
        for (int s = 0; s < Sn; ++s) {
            float v = __fadd_rn(xp[q][s], __fmul_rn(s2[lin[q][s]], vyv[q]));
            sum = __fadd_rn(sum, v);
            c += (v > 0.05f) ? 1 : 0;
        }
        float outv = 0.0f;
        if (pv[q]) {
            float mean = sum / 10.0f;
            float ratio = (float)c / 10.0f;
            if (mean > 0.0f && ratio > 0.8f)
                outv = mean + halfs[q];
        }
        if (act) co[pr] = outv;
    }
}

// ---------------------------------------------------------------------------
extern "C" void kernel_launch(void* const* d_in, const int* in_sizes, int n_in,
                              void* d_out, int out_size)
{
    const float* heat = (const float*)d_in[0];
    const float* paf  = (const float*)d_in[1];
    float* out   = (float*)d_out;
    float* peaks = out;                                  // B*K*P*3 = 48960
    float* conn  = out + (size_t)Bdim * Kdim * Pn * 3;   // B*L*P*P = 547200

    const int smem1 = CAP * 8 + NBINS * 4;               // 53248 -> 4 blocks/SM
    const int smem2 = HW * 4;                            // 102400 -> 2 blocks/SM
    cudaFuncSetAttribute(stage1_kernel, cudaFuncAttributeMaxDynamicSharedMemorySize, smem1);
    cudaFuncSetAttribute(stage2_kernel, cudaFuncAttributeMaxDynamicSharedMemorySize, smem2);

    stage1_kernel<<<Bdim * Kdim, T1, smem1>>>(heat, peaks);
    stage2_kernel<<<Bdim * Ln, T2, smem2>>>(paf, peaks, conn);
}